// round 1
// baseline (speedup 1.0000x reference)
#include <cuda_runtime.h>

#define NB 2
#define SB 1024
#define HB 12
#define DB 64
#define HID (HB*DB)            // 768
#define NCHUNK 8               // split-K chunks for pv
#define SCHUNK (SB/NCHUNK)     // 128
#define LCHUNK 16

#define PPV_ELEMS (NB*SB*HB*DB*DB)   // 100663296
#define Z_OFF PPV_ELEMS

__device__ float g_p[NB*SB*HID];                 // p feature map [n][s][h*64+d]
__device__ float g_psum[NB*HID];                 // sum over s
__device__ float g_pvpart[NCHUNK*NB*HB*DB*DB];   // split-K partials
__device__ float g_pv[NB*HB*DB*DB];              // pv[n][h][m][d] (head_mask applied)

// ---------------------------------------------------------------------------
// K1: p[n,s,h,d] = (elu(pw[s,h*64+d]) + 1) * mask[n,s]
//     elu(x)+1 = (x>0) ? x+1 : exp(x)
// ---------------------------------------------------------------------------
__global__ void k_feat(const float* __restrict__ pw, const float* __restrict__ mask) {
    int e4 = blockIdx.x * blockDim.x + threadIdx.x;   // 196608 float4s
    if (e4 >= SB * HID / 4) return;
    int s = e4 / (HID / 4);
    float4 x = reinterpret_cast<const float4*>(pw)[e4];
    float4 f;
    f.x = x.x > 0.f ? x.x + 1.f : expf(x.x);
    f.y = x.y > 0.f ? x.y + 1.f : expf(x.y);
    f.z = x.z > 0.f ? x.z + 1.f : expf(x.z);
    f.w = x.w > 0.f ? x.w + 1.f : expf(x.w);
    float m0 = mask[s];
    float m1 = mask[SB + s];
    float4 a = make_float4(f.x * m0, f.y * m0, f.z * m0, f.w * m0);
    float4 b = make_float4(f.x * m1, f.y * m1, f.z * m1, f.w * m1);
    reinterpret_cast<float4*>(g_p)[e4] = a;
    reinterpret_cast<float4*>(g_p)[SB * HID / 4 + e4] = b;
}

// ---------------------------------------------------------------------------
// K2: psum[n][hd] = sum_s p[n][s][hd]
// ---------------------------------------------------------------------------
__global__ void k_psum() {
    int i = blockIdx.x * blockDim.x + threadIdx.x;    // 1536
    if (i >= NB * HID) return;
    int n = i / HID;
    int hd = i % HID;
    const float* base = g_p + (size_t)n * SB * HID + hd;
    float acc = 0.f;
    #pragma unroll 8
    for (int s = 0; s < SB; s++) acc += base[(size_t)s * HID];
    g_psum[i] = acc;
}

// ---------------------------------------------------------------------------
// K3: pv partials — pvpart[c][n][h][m][d] = sum_{s in chunk c} v[n,s,h,m]*p[n,s,h,d]
// grid (NCHUNK, H, N), 256 threads, each thread a 4x4 (m,d) tile
// ---------------------------------------------------------------------------
__global__ void k_pv_part(const float* __restrict__ v) {
    int c = blockIdx.x, h = blockIdx.y, n = blockIdx.z;
    int t = threadIdx.x;
    int tm = t >> 4;     // 0..15 -> m base = tm*4
    int td = t & 15;     // 0..15 -> d base = td*4

    __shared__ float vs[8][DB];
    __shared__ float ps[8][DB];

    float acc[4][4];
    #pragma unroll
    for (int i = 0; i < 4; i++)
        #pragma unroll
        for (int j = 0; j < 4; j++) acc[i][j] = 0.f;

    int s0 = c * SCHUNK;
    for (int so = 0; so < SCHUNK; so += 8) {
        // load 8 rows of v and p (each 64 floats) into shared
        {
            int which = t >> 7;          // 0: v, 1: p
            int slot  = t & 127;         // 128 float4s per array
            int row   = slot >> 4;
            int col4  = slot & 15;
            size_t g4 = ((size_t)((n * SB + s0 + so + row) * HB + h) * DB) / 4 + col4;
            float4 val = which == 0 ? reinterpret_cast<const float4*>(v)[g4]
                                    : reinterpret_cast<const float4*>(g_p)[g4];
            float* dst = which == 0 ? &vs[row][col4 * 4] : &ps[row][col4 * 4];
            *reinterpret_cast<float4*>(dst) = val;
        }
        __syncthreads();
        #pragma unroll
        for (int ss = 0; ss < 8; ss++) {
            float4 vr = *reinterpret_cast<const float4*>(&vs[ss][tm * 4]);
            float4 pr = *reinterpret_cast<const float4*>(&ps[ss][td * 4]);
            float vv[4] = {vr.x, vr.y, vr.z, vr.w};
            float pp[4] = {pr.x, pr.y, pr.z, pr.w};
            #pragma unroll
            for (int i = 0; i < 4; i++)
                #pragma unroll
                for (int j = 0; j < 4; j++) acc[i][j] += vv[i] * pp[j];
        }
        __syncthreads();
    }

    float* out = g_pvpart + (size_t)c * (NB * HB * DB * DB)
               + ((size_t)(n * HB + h) * DB) * DB;
    #pragma unroll
    for (int i = 0; i < 4; i++) {
        #pragma unroll
        for (int j = 0; j < 4; j++)
            out[(tm * 4 + i) * DB + td * 4 + j] = acc[i][j];
    }
}

// ---------------------------------------------------------------------------
// K3b: reduce partials, apply head_mask
// ---------------------------------------------------------------------------
__global__ void k_pv_reduce(const float* __restrict__ head_mask) {
    int idx = blockIdx.x * blockDim.x + threadIdx.x;   // 98304
    if (idx >= NB * HB * DB * DB) return;
    int h = (idx >> 12) % HB;   // idx/4096 = n*H+h
    float acc = 0.f;
    #pragma unroll
    for (int c = 0; c < NCHUNK; c++)
        acc += g_pvpart[(size_t)c * (NB * HB * DB * DB) + idx];
    g_pv[idx] = acc * head_mask[h];
}

// ---------------------------------------------------------------------------
// K4: z_pp[n,l,h] = dot(p[n,l,h,:], psum[n,h,:]) + eps   (warp per output)
// ---------------------------------------------------------------------------
__global__ void k_z(float* __restrict__ out) {
    int w = blockIdx.x * (blockDim.x / 32) + (threadIdx.x >> 5);   // 24576 warps
    int lane = threadIdx.x & 31;
    if (w >= NB * SB * HB) return;
    int h = w % HB;
    int nl = w / HB;          // n*S + l
    int n = nl / SB;
    const float* pb  = g_p + (size_t)nl * HID + h * DB;
    const float* psb = g_psum + (size_t)n * HID + h * DB;
    float a = pb[lane] * psb[lane] + pb[lane + 32] * psb[lane + 32];
    #pragma unroll
    for (int o = 16; o > 0; o >>= 1) a += __shfl_down_sync(0xffffffffu, a, o);
    if (lane == 0) out[Z_OFF + w] = a + 1e-6f;
}

// ---------------------------------------------------------------------------
// K5 (dominant, store-bound): ppv[n,l,h,m,d] = p[n,l,h,d] * pv[n,h,m,d]
// grid (S/LCHUNK, H, N); block caches pv[n,h] tile (16KB) + 16 p rows (4KB)
// ---------------------------------------------------------------------------
__global__ void __launch_bounds__(256, 4) k_ppv(float* __restrict__ out) {
    int l0 = blockIdx.x * LCHUNK;
    int h  = blockIdx.y;
    int n  = blockIdx.z;
    int t  = threadIdx.x;

    __shared__ float4 pv_sh[DB * DB / 4];   // 1024 float4 = 16KB, index m*16+d4
    __shared__ float4 p_sh[LCHUNK * DB / 4]; // 256 float4 = 4KB, index li*16+d4

    // load pv tile
    {
        const float4* pv4 = reinterpret_cast<const float4*>(g_pv)
                          + (size_t)(n * HB + h) * (DB * DB / 4);
        #pragma unroll
        for (int i = 0; i < 4; i++) pv_sh[t + 256 * i] = pv4[t + 256 * i];
    }
    // load 16 p rows for this l chunk
    {
        int li  = t >> 4;
        int d4  = t & 15;
        const float4* p4 = reinterpret_cast<const float4*>(g_p);
        p_sh[t] = p4[((size_t)((n * SB + l0 + li) * HB + h) * DB) / 4 + d4];
    }
    __syncthreads();

    // hoist this thread's 4 pv float4s into registers
    float4 vv[4];
    #pragma unroll
    for (int i = 0; i < 4; i++) vv[i] = pv_sh[t + 256 * i];

    float4* out4 = reinterpret_cast<float4*>(out);
    #pragma unroll 2
    for (int li = 0; li < LCHUNK; li++) {
        size_t ob = (size_t)((n * SB + l0 + li) * HB + h) * (DB * DB / 4);
        #pragma unroll
        for (int i = 0; i < 4; i++) {
            int w = t + 256 * i;
            int d4 = w & 15;
            float4 pp = p_sh[(li << 4) + d4];
            float4 r;
            r.x = pp.x * vv[i].x;
            r.y = pp.y * vv[i].y;
            r.z = pp.z * vv[i].z;
            r.w = pp.w * vv[i].w;
            __stcs(&out4[ob + w], r);   // streaming store: keep pv/p hot in L2
        }
    }
}

// ---------------------------------------------------------------------------
extern "C" void kernel_launch(void* const* d_in, const int* in_sizes, int n_in,
                              void* d_out, int out_size) {
    // inputs (metadata order): q, v, attention_mask, head_mask, pos_weight
    const float* v         = (const float*)d_in[1];
    const float* mask      = (const float*)d_in[2];
    const float* head_mask = (const float*)d_in[3];
    const float* pw        = (const float*)d_in[4];
    float* out = (float*)d_out;

    k_feat<<<(SB * HID / 4 + 255) / 256, 256>>>(pw, mask);
    k_psum<<<(NB * HID + 255) / 256, 256>>>();
    k_pv_part<<<dim3(NCHUNK, HB, NB), 256>>>(v);
    k_pv_reduce<<<(NB * HB * DB * DB + 255) / 256, 256>>>(head_mask);
    k_z<<<(NB * SB * HB / 8 + 0), 256>>>(out);
    k_ppv<<<dim3(SB / LCHUNK, HB, NB), 256>>>(out);
}

// round 2
// speedup vs baseline: 1.0638x; 1.0638x over previous
#include <cuda_runtime.h>

#define NB 2
#define SB 1024
#define HB 12
#define DB 64
#define HID (HB*DB)            // 768
#define NCHUNK 8               // split-K chunks for pv
#define SCHUNK (SB/NCHUNK)     // 128
#define PSCHUNK 16             // split-S chunks for psum
#define PSLEN (SB/PSCHUNK)     // 64
#define LCHUNK 16

#define PPV_ELEMS (NB*SB*HB*DB*DB)   // 100663296
#define Z_OFF PPV_ELEMS

__device__ float g_p[NB*SB*HID];                  // p feature map [n][s][h*64+d]
__device__ float g_psumpart[PSCHUNK*NB*HID];      // psum partials [c][n*HID+hd]
__device__ float g_psum[NB*HID];                  // sum over s
__device__ float g_pvpart[NCHUNK*NB*HB*DB*DB];    // split-K partials
__device__ float g_pv[NB*HB*DB*DB];               // pv[n][h][m][d] (head_mask applied)

// ---------------------------------------------------------------------------
// K1: p[n,s,h,d] = (elu(pw[s,h*64+d]) + 1) * mask[n,s]
// ---------------------------------------------------------------------------
__global__ void k_feat(const float* __restrict__ pw, const float* __restrict__ mask) {
    int e4 = blockIdx.x * blockDim.x + threadIdx.x;   // 196608 float4s
    if (e4 >= SB * HID / 4) return;
    int s = e4 / (HID / 4);
    float4 x = reinterpret_cast<const float4*>(pw)[e4];
    float4 f;
    f.x = x.x > 0.f ? x.x + 1.f : expf(x.x);
    f.y = x.y > 0.f ? x.y + 1.f : expf(x.y);
    f.z = x.z > 0.f ? x.z + 1.f : expf(x.z);
    f.w = x.w > 0.f ? x.w + 1.f : expf(x.w);
    float m0 = mask[s];
    float m1 = mask[SB + s];
    float4 a = make_float4(f.x * m0, f.y * m0, f.z * m0, f.w * m0);
    float4 b = make_float4(f.x * m1, f.y * m1, f.z * m1, f.w * m1);
    reinterpret_cast<float4*>(g_p)[e4] = a;
    reinterpret_cast<float4*>(g_p)[SB * HID / 4 + e4] = b;
}

// ---------------------------------------------------------------------------
// K2: psum partials — g_psumpart[c][n*HID+hd] = sum_{s in chunk} p[n][s][hd]
// grid: (PSCHUNK * NB*HID/256) = 16*6 = 96 blocks
// ---------------------------------------------------------------------------
__global__ void k_psum_part() {
    int b = blockIdx.x;
    int c   = b / (NB * HID / 256);          // 0..15
    int seg = b % (NB * HID / 256);          // 0..5
    int i   = seg * 256 + threadIdx.x;       // 0..1535 = n*HID+hd
    int n = i / HID;
    int hd = i % HID;
    const float* base = g_p + (size_t)n * SB * HID + (size_t)c * PSLEN * HID + hd;
    float acc = 0.f;
    #pragma unroll 8
    for (int s = 0; s < PSLEN; s++) acc += base[(size_t)s * HID];
    g_psumpart[(size_t)c * (NB * HID) + i] = acc;
}

// ---------------------------------------------------------------------------
// K3: pv partials — pvpart[c][n][h][m][d] = sum_{s in chunk c} v[n,s,h,m]*p[n,s,h,d]
// ---------------------------------------------------------------------------
__global__ void k_pv_part(const float* __restrict__ v) {
    int c = blockIdx.x, h = blockIdx.y, n = blockIdx.z;
    int t = threadIdx.x;
    int tm = t >> 4;
    int td = t & 15;

    __shared__ float vs[8][DB];
    __shared__ float ps[8][DB];

    float acc[4][4];
    #pragma unroll
    for (int i = 0; i < 4; i++)
        #pragma unroll
        for (int j = 0; j < 4; j++) acc[i][j] = 0.f;

    int s0 = c * SCHUNK;
    for (int so = 0; so < SCHUNK; so += 8) {
        {
            int which = t >> 7;
            int slot  = t & 127;
            int row   = slot >> 4;
            int col4  = slot & 15;
            size_t g4 = ((size_t)((n * SB + s0 + so + row) * HB + h) * DB) / 4 + col4;
            float4 val = which == 0 ? reinterpret_cast<const float4*>(v)[g4]
                                    : reinterpret_cast<const float4*>(g_p)[g4];
            float* dst = which == 0 ? &vs[row][col4 * 4] : &ps[row][col4 * 4];
            *reinterpret_cast<float4*>(dst) = val;
        }
        __syncthreads();
        #pragma unroll
        for (int ss = 0; ss < 8; ss++) {
            float4 vr = *reinterpret_cast<const float4*>(&vs[ss][tm * 4]);
            float4 pr = *reinterpret_cast<const float4*>(&ps[ss][td * 4]);
            float vv[4] = {vr.x, vr.y, vr.z, vr.w};
            float pp[4] = {pr.x, pr.y, pr.z, pr.w};
            #pragma unroll
            for (int i = 0; i < 4; i++)
                #pragma unroll
                for (int j = 0; j < 4; j++) acc[i][j] += vv[i] * pp[j];
        }
        __syncthreads();
    }

    float* out = g_pvpart + (size_t)c * (NB * HB * DB * DB)
               + ((size_t)(n * HB + h) * DB) * DB;
    #pragma unroll
    for (int i = 0; i < 4; i++)
        #pragma unroll
        for (int j = 0; j < 4; j++)
            out[(tm * 4 + i) * DB + td * 4 + j] = acc[i][j];
}

// ---------------------------------------------------------------------------
// K4: combined reduce (float4-vectorized):
//   idx < 24576 : g_pv4[idx] = head_mask[h] * sum_c g_pvpart4[c][idx]
//   idx in [24576, 24960) : g_psum4[j] = sum_c g_psumpart4[c][j]
// ---------------------------------------------------------------------------
__global__ void k_reduce(const float* __restrict__ head_mask) {
    int idx = blockIdx.x * blockDim.x + threadIdx.x;
    const int PV4 = NB * HB * DB * DB / 4;   // 24576
    const int PS4 = NB * HID / 4;            // 384
    if (idx < PV4) {
        float4 acc = make_float4(0.f, 0.f, 0.f, 0.f);
        #pragma unroll
        for (int c = 0; c < NCHUNK; c++) {
            float4 x = reinterpret_cast<const float4*>(g_pvpart)[(size_t)c * PV4 + idx];
            acc.x += x.x; acc.y += x.y; acc.z += x.z; acc.w += x.w;
        }
        int h = (idx >> 10) % HB;            // idx*4/4096
        float hm = head_mask[h];
        acc.x *= hm; acc.y *= hm; acc.z *= hm; acc.w *= hm;
        reinterpret_cast<float4*>(g_pv)[idx] = acc;
    } else if (idx < PV4 + PS4) {
        int j = idx - PV4;
        float4 acc = make_float4(0.f, 0.f, 0.f, 0.f);
        #pragma unroll
        for (int c = 0; c < PSCHUNK; c++) {
            float4 x = reinterpret_cast<const float4*>(g_psumpart)[(size_t)c * PS4 + j];
            acc.x += x.x; acc.y += x.y; acc.z += x.z; acc.w += x.w;
        }
        reinterpret_cast<float4*>(g_psum)[j] = acc;
    }
}

// ---------------------------------------------------------------------------
// K5 (dominant, store-bound): ppv[n,l,h,m,d] = p[n,l,h,d] * pv[n,h,m,d]
// Fused: z_pp[n,l,h] = dot(p[n,l,h,:], psum[n,h,:]) + eps
// grid (S/LCHUNK, H, N)
// ---------------------------------------------------------------------------
__global__ void __launch_bounds__(256, 6) k_ppv(float* __restrict__ out) {
    int l0 = blockIdx.x * LCHUNK;
    int h  = blockIdx.y;
    int n  = blockIdx.z;
    int t  = threadIdx.x;

    __shared__ float4 pv_sh[DB * DB / 4];     // 16KB, index m*16+d4
    __shared__ float4 p_sh[LCHUNK * DB / 4];  // 4KB, index li*16+d4
    __shared__ float4 ps_sh[DB / 4];          // 256B, psum row for (n,h)

    {
        const float4* pv4 = reinterpret_cast<const float4*>(g_pv)
                          + (size_t)(n * HB + h) * (DB * DB / 4);
        #pragma unroll
        for (int i = 0; i < 4; i++) pv_sh[t + 256 * i] = pv4[t + 256 * i];
    }
    {
        int li  = t >> 4;
        int d4  = t & 15;
        const float4* p4 = reinterpret_cast<const float4*>(g_p);
        p_sh[t] = p4[((size_t)((n * SB + l0 + li) * HB + h) * DB) / 4 + d4];
    }
    if (t < DB / 4) {
        ps_sh[t] = reinterpret_cast<const float4*>(g_psum)[(n * HID + h * DB) / 4 + t];
    }
    __syncthreads();

    // fused z: 16 outputs, one per li; 16-lane segments reduce 64-elem dots
    {
        int li = t >> 4;
        int j  = t & 15;
        float4 pp = p_sh[(li << 4) + j];
        float4 ss = ps_sh[j];
        float a = pp.x * ss.x + pp.y * ss.y + pp.z * ss.z + pp.w * ss.w;
        a += __shfl_down_sync(0xffffffffu, a, 8, 16);
        a += __shfl_down_sync(0xffffffffu, a, 4, 16);
        a += __shfl_down_sync(0xffffffffu, a, 2, 16);
        a += __shfl_down_sync(0xffffffffu, a, 1, 16);
        if (j == 0)
            out[Z_OFF + (size_t)(n * SB + l0 + li) * HB + h] = a + 1e-6f;
    }

    // hoist this thread's 4 pv float4s into registers
    float4 vv[4];
    #pragma unroll
    for (int i = 0; i < 4; i++) vv[i] = pv_sh[t + 256 * i];

    float4* out4 = reinterpret_cast<float4*>(out);
    #pragma unroll 2
    for (int li = 0; li < LCHUNK; li++) {
        size_t ob = (size_t)((n * SB + l0 + li) * HB + h) * (DB * DB / 4);
        #pragma unroll
        for (int i = 0; i < 4; i++) {
            int w = t + 256 * i;
            int d4 = w & 15;
            float4 pp = p_sh[(li << 4) + d4];
            float4 r;
            r.x = pp.x * vv[i].x;
            r.y = pp.y * vv[i].y;
            r.z = pp.z * vv[i].z;
            r.w = pp.w * vv[i].w;
            __stcs(&out4[ob + w], r);   // streaming store
        }
    }
}

// ---------------------------------------------------------------------------
extern "C" void kernel_launch(void* const* d_in, const int* in_sizes, int n_in,
                              void* d_out, int out_size) {
    // inputs (metadata order): q, v, attention_mask, head_mask, pos_weight
    const float* v         = (const float*)d_in[1];
    const float* mask      = (const float*)d_in[2];
    const float* head_mask = (const float*)d_in[3];
    const float* pw        = (const float*)d_in[4];
    float* out = (float*)d_out;

    k_feat<<<(SB * HID / 4 + 255) / 256, 256>>>(pw, mask);
    k_psum_part<<<PSCHUNK * (NB * HID / 256), 256>>>();
    k_pv_part<<<dim3(NCHUNK, HB, NB), 256>>>(v);
    k_reduce<<<(NB * HB * DB * DB / 4 + NB * HID / 4 + 255) / 256, 256>>>(head_mask);
    k_ppv<<<dim3(SB / LCHUNK, HB, NB), 256>>>(out);
}

// round 3
// speedup vs baseline: 1.3505x; 1.2695x over previous
#include <cuda_runtime.h>

#define NB 2
#define SB 1024
#define HB 12
#define DB 64
#define HID (HB*DB)            // 768
#define NCHUNK 8               // split-K chunks for pv + psum
#define SCHUNK (SB/NCHUNK)     // 128
#define LCHUNK 16

#define PPV_ELEMS (NB*SB*HB*DB*DB)   // 100663296
#define Z_OFF PPV_ELEMS

__device__ float g_p[NB*SB*HID];                  // p feature map [n][s][h*64+d]
__device__ float g_psumpart[NCHUNK*NB*HB*DB];     // psum partials [c][n][h][d]
__device__ float g_psum[NB*HID];                  // sum over s  [n][h*64+d]
__device__ float g_pvpart[NCHUNK*NB*HB*DB*DB];    // split-K partials
__device__ float g_pv[NB*HB*DB*DB];               // pv[n][h][m][d] (head_mask applied)

// ---------------------------------------------------------------------------
// K1: p[n,s,h,d] = (elu(pw[s,h*64+d]) + 1) * mask[n,s]
// ---------------------------------------------------------------------------
__global__ void k_feat(const float* __restrict__ pw, const float* __restrict__ mask) {
    int e4 = blockIdx.x * blockDim.x + threadIdx.x;   // 196608 float4s
    if (e4 >= SB * HID / 4) return;
    int s = e4 / (HID / 4);
    float4 x = reinterpret_cast<const float4*>(pw)[e4];
    float4 f;
    f.x = x.x > 0.f ? x.x + 1.f : expf(x.x);
    f.y = x.y > 0.f ? x.y + 1.f : expf(x.y);
    f.z = x.z > 0.f ? x.z + 1.f : expf(x.z);
    f.w = x.w > 0.f ? x.w + 1.f : expf(x.w);
    float m0 = mask[s];
    float m1 = mask[SB + s];
    float4 a = make_float4(f.x * m0, f.y * m0, f.z * m0, f.w * m0);
    float4 b = make_float4(f.x * m1, f.y * m1, f.z * m1, f.w * m1);
    reinterpret_cast<float4*>(g_p)[e4] = a;
    reinterpret_cast<float4*>(g_p)[SB * HID / 4 + e4] = b;
}

// ---------------------------------------------------------------------------
// K2: pv partials + psum partials fused.
//   pvpart[c][n][h][m][d] = sum_{s in chunk c} v[n,s,h,m] * p[n,s,h,d]
//   psumpart[c][n][h][d]  = sum_{s in chunk c} p[n,s,h,d]
// grid (NCHUNK, H, N), 256 threads
// ---------------------------------------------------------------------------
__global__ void k_pv_part(const float* __restrict__ v) {
    int c = blockIdx.x, h = blockIdx.y, n = blockIdx.z;
    int t = threadIdx.x;
    int tm = t >> 4;
    int td = t & 15;

    __shared__ float vs[8][DB];
    __shared__ float ps[8][DB];

    float acc[4][4];
    #pragma unroll
    for (int i = 0; i < 4; i++)
        #pragma unroll
        for (int j = 0; j < 4; j++) acc[i][j] = 0.f;
    float psacc = 0.f;   // column sum for threads t<64

    int s0 = c * SCHUNK;
    for (int so = 0; so < SCHUNK; so += 8) {
        {
            int which = t >> 7;
            int slot  = t & 127;
            int row   = slot >> 4;
            int col4  = slot & 15;
            size_t g4 = ((size_t)((n * SB + s0 + so + row) * HB + h) * DB) / 4 + col4;
            float4 val = which == 0 ? reinterpret_cast<const float4*>(v)[g4]
                                    : reinterpret_cast<const float4*>(g_p)[g4];
            float* dst = which == 0 ? &vs[row][col4 * 4] : &ps[row][col4 * 4];
            *reinterpret_cast<float4*>(dst) = val;
        }
        __syncthreads();
        #pragma unroll
        for (int ss = 0; ss < 8; ss++) {
            float4 vr = *reinterpret_cast<const float4*>(&vs[ss][tm * 4]);
            float4 pr = *reinterpret_cast<const float4*>(&ps[ss][td * 4]);
            float vv[4] = {vr.x, vr.y, vr.z, vr.w};
            float pp[4] = {pr.x, pr.y, pr.z, pr.w};
            #pragma unroll
            for (int i = 0; i < 4; i++)
                #pragma unroll
                for (int j = 0; j < 4; j++) acc[i][j] += vv[i] * pp[j];
        }
        if (t < DB) {
            #pragma unroll
            for (int ss = 0; ss < 8; ss++) psacc += ps[ss][t];
        }
        __syncthreads();
    }

    float* out = g_pvpart + (size_t)c * (NB * HB * DB * DB)
               + ((size_t)(n * HB + h) * DB) * DB;
    #pragma unroll
    for (int i = 0; i < 4; i++)
        #pragma unroll
        for (int j = 0; j < 4; j++)
            out[(tm * 4 + i) * DB + td * 4 + j] = acc[i][j];

    if (t < DB)
        g_psumpart[(size_t)c * (NB * HB * DB) + ((n * HB + h) << 6) + t] = psacc;
}

// ---------------------------------------------------------------------------
// K3: combined reduce (float4-vectorized, 128-thread blocks for >148 CTAs):
// ---------------------------------------------------------------------------
__global__ void k_reduce(const float* __restrict__ head_mask) {
    int idx = blockIdx.x * blockDim.x + threadIdx.x;
    const int PV4 = NB * HB * DB * DB / 4;   // 24576
    const int PS4 = NB * HID / 4;            // 384
    if (idx < PV4) {
        float4 acc = make_float4(0.f, 0.f, 0.f, 0.f);
        #pragma unroll
        for (int c = 0; c < NCHUNK; c++) {
            float4 x = reinterpret_cast<const float4*>(g_pvpart)[(size_t)c * PV4 + idx];
            acc.x += x.x; acc.y += x.y; acc.z += x.z; acc.w += x.w;
        }
        int h = (idx >> 10) % HB;
        float hm = head_mask[h];
        acc.x *= hm; acc.y *= hm; acc.z *= hm; acc.w *= hm;
        reinterpret_cast<float4*>(g_pv)[idx] = acc;
    } else if (idx < PV4 + PS4) {
        int j = idx - PV4;   // float4 index into [n][h][d]
        float4 acc = make_float4(0.f, 0.f, 0.f, 0.f);
        #pragma unroll
        for (int c = 0; c < NCHUNK; c++) {
            float4 x = reinterpret_cast<const float4*>(g_psumpart)[(size_t)c * (NB * HB * DB / 4) + j];
            acc.x += x.x; acc.y += x.y; acc.z += x.z; acc.w += x.w;
        }
        reinterpret_cast<float4*>(g_psum)[j] = acc;
    }
}

// ---------------------------------------------------------------------------
// K4 (dominant, store-bound): ppv[n,l,h,m,d] = p[n,l,h,d] * pv[n,h,m,d]
// Fused: z_pp[n,l,h] = dot(p[n,l,h,:], psum[n,h,:]) + eps
// 256-bit streaming stores (st.global.cs.v8.f32, sm_100+).
// ---------------------------------------------------------------------------
__device__ __forceinline__ void stg_cs_v8(float* p, float4 a, float4 b) {
    asm volatile("st.global.cs.v8.f32 [%0], {%1,%2,%3,%4,%5,%6,%7,%8};"
                 :: "l"(p), "f"(a.x), "f"(a.y), "f"(a.z), "f"(a.w),
                    "f"(b.x), "f"(b.y), "f"(b.z), "f"(b.w) : "memory");
}

__global__ void __launch_bounds__(256, 6) k_ppv(float* __restrict__ out) {
    int l0 = blockIdx.x * LCHUNK;
    int h  = blockIdx.y;
    int n  = blockIdx.z;
    int t  = threadIdx.x;

    __shared__ float4 pv_sh[DB * DB / 4];     // 16KB, index m*16+d4
    __shared__ float4 p_sh[LCHUNK * DB / 4];  // 4KB, index li*16+d4
    __shared__ float4 ps_sh[DB / 4];          // 256B

    {
        const float4* pv4 = reinterpret_cast<const float4*>(g_pv)
                          + (size_t)(n * HB + h) * (DB * DB / 4);
        #pragma unroll
        for (int i = 0; i < 4; i++) pv_sh[t + 256 * i] = pv4[t + 256 * i];
    }
    {
        int li  = t >> 4;
        int d4  = t & 15;
        const float4* p4 = reinterpret_cast<const float4*>(g_p);
        p_sh[t] = p4[((size_t)((n * SB + l0 + li) * HB + h) * DB) / 4 + d4];
    }
    if (t < DB / 4) {
        ps_sh[t] = reinterpret_cast<const float4*>(g_psum)[(n * HID + h * DB) / 4 + t];
    }
    __syncthreads();

    // fused z: 16-lane segmented dot products
    {
        int li = t >> 4;
        int j  = t & 15;
        float4 pp = p_sh[(li << 4) + j];
        float4 ss = ps_sh[j];
        float a = pp.x * ss.x + pp.y * ss.y + pp.z * ss.z + pp.w * ss.w;
        a += __shfl_down_sync(0xffffffffu, a, 8, 16);
        a += __shfl_down_sync(0xffffffffu, a, 4, 16);
        a += __shfl_down_sync(0xffffffffu, a, 2, 16);
        a += __shfl_down_sync(0xffffffffu, a, 1, 16);
        if (j == 0)
            out[Z_OFF + (size_t)(n * SB + l0 + li) * HB + h] = a + 1e-6f;
    }

    // this thread owns two adjacent float4 pairs -> two v8 stores per li.
    // v8 slot w2 in [0,512): covers float4 indices 2*w2, 2*w2+1.
    // thread handles w2 = t and t+256.
    float4 va0 = pv_sh[2 * t];         // d4 = (2t)&15
    float4 va1 = pv_sh[2 * t + 1];
    float4 vb0 = pv_sh[2 * t + 512];
    float4 vb1 = pv_sh[2 * t + 513];
    int da0 = (2 * t) & 15, da1 = (2 * t + 1) & 15;   // db same: (2t+512)&15 == da0

    #pragma unroll 2
    for (int li = 0; li < LCHUNK; li++) {
        float* ob = out + (size_t)((n * SB + l0 + li) * HB + h) * (DB * DB);
        float4 pa0 = p_sh[(li << 4) + da0];
        float4 pa1 = p_sh[(li << 4) + da1];
        float4 r0, r1;
        r0.x = pa0.x * va0.x; r0.y = pa0.y * va0.y; r0.z = pa0.z * va0.z; r0.w = pa0.w * va0.w;
        r1.x = pa1.x * va1.x; r1.y = pa1.y * va1.y; r1.z = pa1.z * va1.z; r1.w = pa1.w * va1.w;
        stg_cs_v8(ob + 8 * t, r0, r1);
        float4 s0, s1;
        s0.x = pa0.x * vb0.x; s0.y = pa0.y * vb0.y; s0.z = pa0.z * vb0.z; s0.w = pa0.w * vb0.w;
        s1.x = pa1.x * vb1.x; s1.y = pa1.y * vb1.y; s1.z = pa1.z * vb1.z; s1.w = pa1.w * vb1.w;
        stg_cs_v8(ob + 8 * t + 2048, s0, s1);
    }
}

// ---------------------------------------------------------------------------
extern "C" void kernel_launch(void* const* d_in, const int* in_sizes, int n_in,
                              void* d_out, int out_size) {
    // inputs (metadata order): q, v, attention_mask, head_mask, pos_weight
    const float* v         = (const float*)d_in[1];
    const float* mask      = (const float*)d_in[2];
    const float* head_mask = (const float*)d_in[3];
    const float* pw        = (const float*)d_in[4];
    float* out = (float*)d_out;

    k_feat<<<(SB * HID / 4 + 255) / 256, 256>>>(pw, mask);
    k_pv_part<<<dim3(NCHUNK, HB, NB), 256>>>(v);
    k_reduce<<<(NB * HB * DB * DB / 4 + NB * HID / 4 + 127) / 128, 128>>>(head_mask);
    k_ppv<<<dim3(SB / LCHUNK, HB, NB), 256>>>(out);
}